// round 15
// baseline (speedup 1.0000x reference)
#include <cuda_runtime.h>
#include <cuda_bf16.h>
#include <cstdint>

#define NA 100000
#define NBND 200000
#define MAXNB 6
#define AF 133
#define BF 147
#define H 256
#define NM 4096
#define MF 200
#define XDIM (H + MF)   /* 456 */
#define F1 512
#define F2 256

#define KP_WI 192
#define KP_WH 256
#define KP_WO 448
#define KP_W1 512
#define KP_W2 512

// ==================== helpers ===============================================
__device__ __forceinline__ uint32_t smem_u32(const void* p) {
    uint32_t a;
    asm("{ .reg .u64 t; cvta.to.shared.u64 t, %1; cvt.u32.u64 %0, t; }" : "=r"(a) : "l"(p));
    return a;
}
#define SWZ(x) ((x) ^ (((x) >> 3) & 0x70))

__device__ __forceinline__ void ldsm_x4(uint32_t& r0, uint32_t& r1, uint32_t& r2, uint32_t& r3,
                                        uint32_t addr) {
    asm volatile("ldmatrix.sync.aligned.m8n8.x4.shared.b16 {%0,%1,%2,%3}, [%4];"
                 : "=r"(r0), "=r"(r1), "=r"(r2), "=r"(r3) : "r"(addr));
}
__device__ __forceinline__ void mma_bf16(float* d, const uint32_t* a, const uint32_t* b) {
    asm volatile("mma.sync.aligned.m16n8k16.row.col.f32.bf16.bf16.f32 "
                 "{%0,%1,%2,%3}, {%4,%5,%6,%7}, {%8,%9}, {%0,%1,%2,%3};"
                 : "+f"(d[0]), "+f"(d[1]), "+f"(d[2]), "+f"(d[3])
                 : "r"(a[0]), "r"(a[1]), "r"(a[2]), "r"(a[3]), "r"(b[0]), "r"(b[1]));
}
#define CP_ASYNC16(dst, src) \
    asm volatile("cp.async.cg.shared.global [%0], [%1], 16;" :: "r"(dst), "l"(src))
#define CP_COMMIT() asm volatile("cp.async.commit_group;" ::: "memory")
#define CP_WAIT0()  asm volatile("cp.async.wait_group 0;" ::: "memory")

// split one float4 into bf16 hi/lo packed pairs
__device__ __forceinline__ void split4(float4 v, uint2& hv, uint2& lv) {
    __nv_bfloat162 h01 = __floats2bfloat162_rn(v.x, v.y);
    __nv_bfloat162 h23 = __floats2bfloat162_rn(v.z, v.w);
    uint32_t u01 = *(uint32_t*)&h01, u23 = *(uint32_t*)&h23;
    float hx = __uint_as_float(u01 << 16);
    float hy = __uint_as_float(u01 & 0xFFFF0000u);
    float hz = __uint_as_float(u23 << 16);
    float hw = __uint_as_float(u23 & 0xFFFF0000u);
    __nv_bfloat162 l01 = __floats2bfloat162_rn(v.x - hx, v.y - hy);
    __nv_bfloat162 l23 = __floats2bfloat162_rn(v.z - hz, v.w - hw);
    hv = make_uint2(u01, u23);
    lv = make_uint2(*(uint32_t*)&l01, *(uint32_t*)&l23);
}
// scalar split
__device__ __forceinline__ void split1(float x, unsigned short& h, unsigned short& l) {
    __nv_bfloat16 hb = __float2bfloat16(x);
    h = __bfloat16_as_ushort(hb);
    l = __bfloat16_as_ushort(__float2bfloat16(x - __bfloat162float(hb)));
}
__device__ __forceinline__ float bfp(unsigned short h, unsigned short l) {
    return __uint_as_float((uint32_t)h << 16) + __uint_as_float((uint32_t)l << 16);
}

// ==================== scratch globals =======================================
__device__ float g_inputs[NBND * H];
__device__ float g_P[NBND * H];
__device__ float g_amsg[NA * H];
__device__ float g_atomh[NA * H];
__device__ float g_molx[NM * XDIM];
__device__ float g_h1[NM * F1];
// activation planes (bf16 hi/lo)
__device__ __nv_bfloat16 g_msgH[NBND * H], g_msgL[NBND * H];
__device__ __nv_bfloat16 g_fbH[NBND * KP_WI], g_fbL[NBND * KP_WI];
// prepped weights [N][Kpad]
__device__ __nv_bfloat16 g_wi_h[H * KP_WI],  g_wi_l[H * KP_WI];
__device__ __nv_bfloat16 g_wh_h[H * KP_WH],  g_wh_l[H * KP_WH];
__device__ __nv_bfloat16 g_wo_h[H * KP_WO],  g_wo_l[H * KP_WO];
__device__ __nv_bfloat16 g_w1_h[F1 * KP_W1], g_w1_l[F1 * KP_W1];
__device__ __nv_bfloat16 g_w2_h[F2 * KP_W2], g_w2_l[F2 * KP_W2];

// ==================== prep kernels ==========================================
__global__ void prep_w(const float* __restrict__ W, __nv_bfloat16* __restrict__ hi,
                       __nv_bfloat16* __restrict__ lo, int K, int N, int Kpad) {
    int i = blockIdx.x * blockDim.x + threadIdx.x;
    if (i >= N * Kpad) return;
    int n = i / Kpad, k = i - n * Kpad;
    float x = (k < K) ? W[(long long)k * N + n] : 0.f;
    unsigned short h, l; split1(x, h, l);
    hi[i] = __ushort_as_bfloat16(h);
    lo[i] = __ushort_as_bfloat16(l);
}
// f_bonds [NBND][BF] fp32 -> planes [NBND][KP_WI]
__global__ void prep_fb(const float* __restrict__ fb, __nv_bfloat16* __restrict__ hi,
                        __nv_bfloat16* __restrict__ lo) {
    int i = blockIdx.x * blockDim.x + threadIdx.x;
    if (i >= NBND * KP_WI) return;
    int r = i / KP_WI, k = i - r * KP_WI;
    float x = (k < BF) ? fb[(long long)r * BF + k] : 0.f;
    unsigned short h, l; split1(x, h, l);
    hi[i] = __ushort_as_bfloat16(h);
    lo[i] = __ushort_as_bfloat16(l);
}

// ==================== A-side loaders (convert path) =========================
struct TCDirect {
    const float* __restrict__ A; int ld; int K;
    __device__ __forceinline__ float4 load4(int r, int k) const {
        const float* row = A + (long long)r * ld;
        float4 v;
        v.x = (k     < K) ? row[k]     : 0.f;
        v.y = (k + 1 < K) ? row[k + 1] : 0.f;
        v.z = (k + 2 < K) ? row[k + 2] : 0.f;
        v.w = (k + 3 < K) ? row[k + 3] : 0.f;
        return v;
    }
};
struct TCConcat { // A[r,:] = [f_atoms[r] (133) | amsg[r] (256)], K=389
    const float* __restrict__ fa; const float* __restrict__ amsg;
    __device__ __forceinline__ float4 load4(int r, int k) const {
        float o[4];
#pragma unroll
        for (int i = 0; i < 4; i++) {
            int kk = k + i; float v = 0.f;
            if (kk < AF) v = fa[(long long)r * AF + kk];
            else if (kk < AF + H) v = amsg[(long long)r * H + (kk - AF)];
            o[i] = v;
        }
        return make_float4(o[0], o[1], o[2], o[3]);
    }
};

// ==================== epilogues =============================================
struct EpiBondPS {   // store pre-relu inputs + relu msg as bf16 hi/lo planes
    float* __restrict__ inputs;
    __nv_bfloat16* __restrict__ mh; __nv_bfloat16* __restrict__ ml;
    __device__ __forceinline__ void operator()(int r, int n, float acc) const {
        long long o = (long long)r * H + n;
        inputs[o] = acc;
        unsigned short h, l; split1(fmaxf(acc, 0.f), h, l);
        mh[o] = __ushort_as_bfloat16(h);
        ml[o] = __ushort_as_bfloat16(l);
    }
};
struct EpiStore {
    float* __restrict__ out;
    __device__ __forceinline__ void operator()(int r, int n, float acc) const {
        out[(long long)r * H + n] = acc;
    }
};
struct EpiBias {
    const float* __restrict__ bias; float* __restrict__ out; int ld;
    __device__ __forceinline__ void operator()(int r, int n, float acc) const {
        out[(long long)r * ld + n] = fmaxf(acc + bias[n], 0.f);
    }
};

// ==================== SMEM layout ===========================================
#define ST_AHI 0
#define ST_ALO 8192
#define ST_BHI 16384
#define ST_BLO 32768
#define ST_SIZE 49152
#define SM_TOTAL (2 * ST_SIZE)

// ---- shared compute body (warp tile 32x32, 3-term) -------------------------
template <int NCH_MAX>
struct GemmCore {};

#define GEMM_PROLOGUE() \
    extern __shared__ char smem[]; \
    const uint32_t sb = smem_u32(smem); \
    const int tid = threadIdx.x; \
    const int wid = tid >> 5, lid = tid & 31; \
    const int bm = blockIdx.x * 64; \
    const int ncol = blockIdx.y * 128; \
    const int wm = wid & 1; \
    const int wn = wid >> 1; \
    const int lj = lid >> 3; \
    const int lr = lid & 7; \
    float acc[2][4][4]; \
    _Pragma("unroll") for (int mf = 0; mf < 2; mf++) \
    _Pragma("unroll") for (int nf = 0; nf < 4; nf++) \
    _Pragma("unroll") for (int q = 0; q < 4; q++) acc[mf][nf][q] = 0.f;

#define GEMM_COMPUTE(stg) do { \
    const uint32_t ba = sb + (stg) * ST_SIZE; \
    _Pragma("unroll") \
    for (int kf = 0; kf < 4; kf++) { \
        uint32_t a_hi[2][4], a_lo[2][4]; \
        _Pragma("unroll") \
        for (int mf = 0; mf < 2; mf++) { \
            int row = wm * 32 + mf * 16 + lr + (lj & 1) * 8; \
            uint32_t sw = SWZ((uint32_t)(row * 128 + kf * 32 + (lj >> 1) * 16)); \
            ldsm_x4(a_hi[mf][0], a_hi[mf][1], a_hi[mf][2], a_hi[mf][3], ba + ST_AHI + sw); \
            ldsm_x4(a_lo[mf][0], a_lo[mf][1], a_lo[mf][2], a_lo[mf][3], ba + ST_ALO + sw); \
        } \
        _Pragma("unroll") \
        for (int np = 0; np < 2; np++) { \
            int nrow = wn * 32 + np * 16 + lr + (lj & 1) * 8; \
            uint32_t sw = SWZ((uint32_t)(nrow * 128 + kf * 32 + (lj >> 1) * 16)); \
            uint32_t bh[2][2], bl[2][2]; \
            uint32_t r0, r1, r2, r3; \
            ldsm_x4(r0, r1, r2, r3, ba + ST_BHI + sw); \
            bh[0][0] = r0; bh[0][1] = r2; bh[1][0] = r1; bh[1][1] = r3; \
            ldsm_x4(r0, r1, r2, r3, ba + ST_BLO + sw); \
            bl[0][0] = r0; bl[0][1] = r2; bl[1][0] = r1; bl[1][1] = r3; \
            _Pragma("unroll") \
            for (int mf = 0; mf < 2; mf++) \
            _Pragma("unroll") \
            for (int sub = 0; sub < 2; sub++) { \
                int nf = np * 2 + sub; \
                mma_bf16(acc[mf][nf], a_hi[mf], bh[sub]); \
                mma_bf16(acc[mf][nf], a_hi[mf], bl[sub]); \
                mma_bf16(acc[mf][nf], a_lo[mf], bh[sub]); \
            } \
        } \
    } } while (0)

#define GEMM_EPILOGUE(ep, M) do { \
    const int er = bm + wm * 32 + (lid >> 2); \
    const int ec = ncol + wn * 32 + (lid & 3) * 2; \
    _Pragma("unroll") \
    for (int mf = 0; mf < 2; mf++) { \
        int r0 = er + mf * 16; \
        _Pragma("unroll") \
        for (int nf = 0; nf < 4; nf++) { \
            int c = ec + nf * 8; \
            if (r0 < (M)) { ep(r0, c, acc[mf][nf][0]); ep(r0, c + 1, acc[mf][nf][1]); } \
            if (r0 + 8 < (M)) { ep(r0 + 8, c, acc[mf][nf][2]); ep(r0 + 8, c + 1, acc[mf][nf][3]); } \
        } \
    } } while (0)

#define FILL_B(stg, k0) do { \
    int n = tid >> 1; \
    int half = tid & 1; \
    const char* sh = (const char*)(Bhi + (long long)(ncol + n) * Kpad + (k0)); \
    const char* sl = (const char*)(Blo + (long long)(ncol + n) * Kpad + (k0)); \
    uint32_t rowoff = (uint32_t)(n * 128); \
    uint32_t bhb = sb + (stg) * ST_SIZE + ST_BHI; \
    uint32_t blb = sb + (stg) * ST_SIZE + ST_BLO; \
    _Pragma("unroll") \
    for (int j = 0; j < 4; j++) { \
        int unit = half * 4 + j; \
        uint32_t sw = SWZ(rowoff + unit * 16); \
        CP_ASYNC16(bhb + sw, sh + unit * 16); \
        CP_ASYNC16(blb + sw, sl + unit * 16); \
    } } while (0)

// ==================== GEMM, pre-split A planes (M % 64 == 0) ================
template <class EP>
__global__ __launch_bounds__(256, 2) void tc_gemm_ps(
        const __nv_bfloat16* __restrict__ Ahi, const __nv_bfloat16* __restrict__ Alo,
        int ldA, EP ep,
        const __nv_bfloat16* __restrict__ Bhi, const __nv_bfloat16* __restrict__ Blo,
        int M, int Kpad) {
    GEMM_PROLOGUE();
    const int nch = Kpad / 64;

    auto fillA = [&](int stg, int k0) {
        // A planes: 64 rows x 64 cols bf16 = 128 B/row/plane; 512 cp per plane
#pragma unroll
        for (int rep = 0; rep < 2; rep++) {
            int idx = tid + rep * 256;
            int r = idx >> 3, u = idx & 7;
            uint32_t sw = SWZ((uint32_t)(r * 128 + u * 16));
            const char* srcH = (const char*)(Ahi + (long long)(bm + r) * ldA + k0) + u * 16;
            const char* srcL = (const char*)(Alo + (long long)(bm + r) * ldA + k0) + u * 16;
            CP_ASYNC16(sb + stg * ST_SIZE + ST_AHI + sw, srcH);
            CP_ASYNC16(sb + stg * ST_SIZE + ST_ALO + sw, srcL);
        }
    };

    fillA(0, 0); FILL_B(0, 0);
    CP_COMMIT();
    for (int ch = 0; ch < nch; ch++) {
        int cur = ch & 1;
        CP_WAIT0();
        __syncthreads();
        if (ch + 1 < nch) { fillA(cur ^ 1, (ch + 1) * 64); FILL_B(cur ^ 1, (ch + 1) * 64); CP_COMMIT(); }
        GEMM_COMPUTE(cur);
    }
    GEMM_EPILOGUE(ep, M);
}

// ==================== GEMM, convert-A path (any M) ==========================
template <class AL, class EP>
__global__ __launch_bounds__(256, 2) void tc_gemm(AL al, EP ep,
        const __nv_bfloat16* __restrict__ Bhi, const __nv_bfloat16* __restrict__ Blo,
        int M, int Kpad) {
    GEMM_PROLOGUE();
    const int nch = Kpad / 64;

    auto fillA = [&](int stg, int k0) {
        char* base = smem + stg * ST_SIZE;
#pragma unroll
        for (int it = 0; it < 4; it++) {
            int t = tid + it * 256;
            int r = t >> 4;
            int c4 = (t & 15) << 2;
            float4 v = make_float4(0.f, 0.f, 0.f, 0.f);
            if (bm + r < M) v = al.load4(bm + r, k0 + c4);
            uint2 hv, lv;
            split4(v, hv, lv);
            uint32_t sw = SWZ((uint32_t)(r * 128 + c4 * 2));
            *(uint2*)(base + ST_AHI + sw) = hv;
            *(uint2*)(base + ST_ALO + sw) = lv;
        }
    };

    fillA(0, 0); FILL_B(0, 0);
    CP_COMMIT();
    for (int ch = 0; ch < nch; ch++) {
        int cur = ch & 1;
        CP_WAIT0();
        __syncthreads();
        if (ch + 1 < nch) { fillA(cur ^ 1, (ch + 1) * 64); FILL_B(cur ^ 1, (ch + 1) * 64); CP_COMMIT(); }
        GEMM_COMPUTE(cur);
    }
    GEMM_EPILOGUE(ep, M);
}

// ==================== aggregation / combine / segmean =======================
__global__ __launch_bounds__(256) void aggregate_k(const float* __restrict__ msg,
                                                   const int* __restrict__ a2b,
                                                   float* __restrict__ amsg) {
    int i = blockIdx.x * blockDim.x + threadIdx.x;
    if (i >= NA * (H / 4)) return;
    int a = i >> 6;
    int c = (i & 63) * 4;
    const int* nb = &a2b[a * MAXNB];
    float4 s = make_float4(0.f, 0.f, 0.f, 0.f);
#pragma unroll
    for (int j = 0; j < MAXNB; j++) {
        float4 v = *(const float4*)&msg[(long long)nb[j] * H + c];
        s.x += v.x; s.y += v.y; s.z += v.z; s.w += v.w;
    }
    *(float4*)&amsg[(long long)a * H + c] = s;
}

// aggregate from bf16 hi/lo planes -> fp32 amsg
__global__ __launch_bounds__(256) void aggregate_hl_k(const __nv_bfloat16* __restrict__ mh,
                                                      const __nv_bfloat16* __restrict__ ml,
                                                      const int* __restrict__ a2b,
                                                      float* __restrict__ amsg) {
    int i = blockIdx.x * blockDim.x + threadIdx.x;
    if (i >= NA * (H / 4)) return;
    int a = i >> 6;
    int c = (i & 63) * 4;
    const int* nb = &a2b[a * MAXNB];
    float4 s = make_float4(0.f, 0.f, 0.f, 0.f);
#pragma unroll
    for (int j = 0; j < MAXNB; j++) {
        long long o = (long long)nb[j] * H + c;
        uint2 hv = *(const uint2*)(mh + o);
        uint2 lv = *(const uint2*)(ml + o);
        s.x += bfp((unsigned short)(hv.x & 0xFFFF), (unsigned short)(lv.x & 0xFFFF));
        s.y += bfp((unsigned short)(hv.x >> 16),   (unsigned short)(lv.x >> 16));
        s.z += bfp((unsigned short)(hv.y & 0xFFFF), (unsigned short)(lv.y & 0xFFFF));
        s.w += bfp((unsigned short)(hv.y >> 16),   (unsigned short)(lv.y >> 16));
    }
    *(float4*)&amsg[(long long)a * H + c] = s;
}

// msg planes = split(relu(inputs + aggP[b2a] - P[b2revb]))
__global__ __launch_bounds__(256) void combine_k(const float* __restrict__ inputs,
                                                 const float* __restrict__ aggP,
                                                 const float* __restrict__ P,
                                                 const int* __restrict__ b2a,
                                                 const int* __restrict__ b2revb,
                                                 __nv_bfloat16* __restrict__ mh,
                                                 __nv_bfloat16* __restrict__ ml) {
    int i = blockIdx.x * blockDim.x + threadIdx.x;
    if (i >= NBND * (H / 4)) return;
    int b = i >> 6;
    int c = (i & 63) * 4;
    int ra = b2a[b];
    int rb = b2revb[b];
    float4 vi = *(const float4*)&inputs[(long long)b * H + c];
    float4 va = *(const float4*)&aggP[(long long)ra * H + c];
    float4 vp = *(const float4*)&P[(long long)rb * H + c];
    float4 o;
    o.x = fmaxf(vi.x + va.x - vp.x, 0.f);
    o.y = fmaxf(vi.y + va.y - vp.y, 0.f);
    o.z = fmaxf(vi.z + va.z - vp.z, 0.f);
    o.w = fmaxf(vi.w + va.w - vp.w, 0.f);
    uint2 hv, lv;
    split4(o, hv, lv);
    long long off = (long long)b * H + c;
    *(uint2*)(mh + off) = hv;
    *(uint2*)(ml + off) = lv;
}

__device__ __forceinline__ int lower_bound_i(const int* __restrict__ a, int n, int v) {
    int lo = 0, hi = n;
    while (lo < hi) { int mid = (lo + hi) >> 1; if (a[mid] < v) lo = mid + 1; else hi = mid; }
    return lo;
}
__global__ __launch_bounds__(256) void segmean_k(const float* __restrict__ atomh,
                                                 const int* __restrict__ atom2mol,
                                                 const float* __restrict__ molfeat,
                                                 float* __restrict__ molx) {
    int m = blockIdx.x;
    int tid = threadIdx.x;
    int start = lower_bound_i(atom2mol, NA, m);
    int end = lower_bound_i(atom2mol, NA, m + 1);
    float inv = 1.f / (float)max(end - start, 1);
    float s = 0.f;
    for (int a = start; a < end; a++) s += atomh[(long long)a * H + tid];
    molx[(long long)m * XDIM + tid] = s * inv;
    if (tid < MF) molx[(long long)m * XDIM + H + tid] = molfeat[(long long)m * MF + tid];
}

// ==================== launch ================================================
extern "C" void kernel_launch(void* const* d_in, const int* in_sizes, int n_in,
                              void* d_out, int out_size) {
    (void)in_sizes; (void)n_in; (void)out_size;
    const float* f_atoms  = (const float*)d_in[0];
    const float* f_bonds  = (const float*)d_in[1];
    const int*   a2b      = (const int*)d_in[2];
    const int*   b2a      = (const int*)d_in[3];
    const int*   b2revb   = (const int*)d_in[4];
    const int*   atom2mol = (const int*)d_in[5];
    const float* mol_feat = (const float*)d_in[6];
    const float* W_i      = (const float*)d_in[7];
    const float* W_h      = (const float*)d_in[8];
    const float* W_o_w    = (const float*)d_in[9];
    const float* W_o_b    = (const float*)d_in[10];
    const float* W1       = (const float*)d_in[11];
    const float* b1       = (const float*)d_in[12];
    const float* W2       = (const float*)d_in[13];
    const float* b2       = (const float*)d_in[14];
    float* out = (float*)d_out;

    float *p_inputs, *p_P, *p_amsg, *p_atomh, *p_molx, *p_h1;
    cudaGetSymbolAddress((void**)&p_inputs, g_inputs);
    cudaGetSymbolAddress((void**)&p_P, g_P);
    cudaGetSymbolAddress((void**)&p_amsg, g_amsg);
    cudaGetSymbolAddress((void**)&p_atomh, g_atomh);
    cudaGetSymbolAddress((void**)&p_molx, g_molx);
    cudaGetSymbolAddress((void**)&p_h1, g_h1);
    __nv_bfloat16 *msgH, *msgL, *fbH, *fbL;
    cudaGetSymbolAddress((void**)&msgH, g_msgH);
    cudaGetSymbolAddress((void**)&msgL, g_msgL);
    cudaGetSymbolAddress((void**)&fbH, g_fbH);
    cudaGetSymbolAddress((void**)&fbL, g_fbL);
    __nv_bfloat16 *wi_h, *wi_l, *wh_h, *wh_l, *wo_h, *wo_l, *w1_h, *w1_l, *w2_h, *w2_l;
    cudaGetSymbolAddress((void**)&wi_h, g_wi_h); cudaGetSymbolAddress((void**)&wi_l, g_wi_l);
    cudaGetSymbolAddress((void**)&wh_h, g_wh_h); cudaGetSymbolAddress((void**)&wh_l, g_wh_l);
    cudaGetSymbolAddress((void**)&wo_h, g_wo_h); cudaGetSymbolAddress((void**)&wo_l, g_wo_l);
    cudaGetSymbolAddress((void**)&w1_h, g_w1_h); cudaGetSymbolAddress((void**)&w1_l, g_w1_l);
    cudaGetSymbolAddress((void**)&w2_h, g_w2_h); cudaGetSymbolAddress((void**)&w2_l, g_w2_l);

    cudaFuncSetAttribute(tc_gemm_ps<EpiBondPS>, cudaFuncAttributeMaxDynamicSharedMemorySize, SM_TOTAL);
    cudaFuncSetAttribute(tc_gemm_ps<EpiStore>,  cudaFuncAttributeMaxDynamicSharedMemorySize, SM_TOTAL);
    cudaFuncSetAttribute(tc_gemm<TCConcat, EpiBias>, cudaFuncAttributeMaxDynamicSharedMemorySize, SM_TOTAL);
    cudaFuncSetAttribute(tc_gemm<TCDirect, EpiBias>, cudaFuncAttributeMaxDynamicSharedMemorySize, SM_TOTAL);

    dim3 blk(256);

    // 0) prep: weights + f_bonds split
    prep_w<<<(H * KP_WI + 255) / 256, blk>>>(W_i, wi_h, wi_l, BF, H, KP_WI);
    prep_w<<<(H * KP_WH + 255) / 256, blk>>>(W_h, wh_h, wh_l, H, H, KP_WH);
    prep_w<<<(H * KP_WO + 255) / 256, blk>>>(W_o_w, wo_h, wo_l, AF + H, H, KP_WO);
    prep_w<<<(F1 * KP_W1 + 255) / 256, blk>>>(W1, w1_h, w1_l, XDIM, F1, KP_W1);
    prep_w<<<(F2 * KP_W2 + 255) / 256, blk>>>(W2, w2_h, w2_l, F1, F2, KP_W2);
    prep_fb<<<(NBND * KP_WI + 255) / 256, blk>>>(f_bonds, fbH, fbL);

    const int MB_BND = NBND / 64;   // 3125
    const int MB_A   = (NA + 63) / 64;
    const int aggBlocks = (NA * (H / 4) + 255) / 256;
    const int cmbBlocks = (NBND * (H / 4) + 255) / 256;

    // 1) inputs = f_bonds @ W_i ; msg planes = split(relu(inputs))
    tc_gemm_ps<<<dim3(MB_BND, H / 128), blk, SM_TOTAL>>>(fbH, fbL, KP_WI,
        EpiBondPS{p_inputs, msgH, msgL}, wi_h, wi_l, NBND, KP_WI);

    // 2-3) message iterations via linearity
    for (int it = 0; it < 2; it++) {
        tc_gemm_ps<<<dim3(MB_BND, H / 128), blk, SM_TOTAL>>>(msgH, msgL, H,
            EpiStore{p_P}, wh_h, wh_l, NBND, KP_WH);
        aggregate_k<<<aggBlocks, blk>>>(p_P, a2b, p_amsg);
        combine_k<<<cmbBlocks, blk>>>(p_inputs, p_amsg, p_P, b2a, b2revb, msgH, msgL);
    }

    // 4) final aggregation (from planes) + atom readout
    aggregate_hl_k<<<aggBlocks, blk>>>(msgH, msgL, a2b, p_amsg);
    tc_gemm<<<dim3(MB_A, H / 128), blk, SM_TOTAL>>>(TCConcat{f_atoms, p_amsg},
        EpiBias{W_o_b, p_atomh, H}, wo_h, wo_l, NA, KP_WO);

    // 5) per-molecule mean + feature concat
    segmean_k<<<NM, blk>>>(p_atomh, atom2mol, mol_feat, p_molx);

    // 6) FFNN layer 1
    tc_gemm<<<dim3(NM / 64, F1 / 128), blk, SM_TOTAL>>>(TCDirect{p_molx, XDIM, XDIM},
        EpiBias{b1, p_h1, F1}, w1_h, w1_l, NM, KP_W1);

    // 7) FFNN layer 2
    tc_gemm<<<dim3(NM / 64, F2 / 128), blk, SM_TOTAL>>>(TCDirect{p_h1, F1, F1},
        EpiBias{b2, out, F2}, w2_h, w2_l, NM, KP_W2);
}